// round 1
// baseline (speedup 1.0000x reference)
#include <cuda_runtime.h>

#define BB 4
#define NN 8192
#define DD 32
#define KNB 16
#define M0 32
#define M1 32
#define M2 64
#define LEAKY 0.1f
#define TILE 2048

__device__ float4 g_xyzw[BB * NN];
__device__ float  g_feat[BB * NN * M0];
__device__ int    g_idx[BB * NN * KNB];

__device__ __forceinline__ float lrelu(float x) { return x > 0.f ? x : LEAKY * x; }

// ---------------------------------------------------------------------------
// Kernel 1: pack xyz as float4(x,y,z,|p|^2) and precompute feat = W0[:,3:] @ points
// grid: B*N/128 blocks of 128 threads; thread -> one point
// ---------------------------------------------------------------------------
__global__ void prep_kernel(const float* __restrict__ xyz,
                            const float* __restrict__ points,
                            const float* __restrict__ W0) {
    __shared__ __align__(16) float wfT[DD][M0];  // wfT[c][o] = W0[o][3+c]
    int tid = threadIdx.x;
    for (int i = tid; i < DD * M0; i += 128) {
        int c = i / M0, o = i % M0;
        wfT[c][o] = W0[o * 35 + 3 + c];
    }
    __syncthreads();

    int gq = blockIdx.x * 128 + tid;       // 0 .. B*N-1
    int b = gq / NN, n = gq % NN;

    const float* xb = xyz + (size_t)b * 3 * NN;
    float x = xb[n], y = xb[NN + n], z = xb[2 * NN + n];
    float sq = fmaf(x, x, fmaf(y, y, z * z));
    g_xyzw[gq] = make_float4(x, y, z, sq);

    float acc[M0];
#pragma unroll
    for (int o = 0; o < M0; o++) acc[o] = 0.f;

    const float* pb = points + (size_t)b * DD * NN + n;
#pragma unroll 4
    for (int c = 0; c < DD; c++) {
        float p = pb[(size_t)c * NN];
        const float4* w4 = (const float4*)wfT[c];
#pragma unroll
        for (int o4 = 0; o4 < M0 / 4; o4++) {
            float4 w = w4[o4];
            acc[o4 * 4 + 0] = fmaf(w.x, p, acc[o4 * 4 + 0]);
            acc[o4 * 4 + 1] = fmaf(w.y, p, acc[o4 * 4 + 1]);
            acc[o4 * 4 + 2] = fmaf(w.z, p, acc[o4 * 4 + 2]);
            acc[o4 * 4 + 3] = fmaf(w.w, p, acc[o4 * 4 + 3]);
        }
    }
    float4* fo = (float4*)(g_feat + (size_t)gq * M0);
#pragma unroll
    for (int o4 = 0; o4 < M0 / 4; o4++)
        fo[o4] = make_float4(acc[o4 * 4 + 0], acc[o4 * 4 + 1],
                             acc[o4 * 4 + 2], acc[o4 * 4 + 3]);
}

// ---------------------------------------------------------------------------
// Kernel 2: kNN top-16 (smallest squared distance, d = sq_n + sq_m - 2 x.y)
// grid: (N/256, B), block 256 threads, 1 thread = 1 query.
// Candidates staged through smem tiles; all threads read the same candidate
// per iteration -> LDS broadcast. Register insertion sort keeps top-16;
// ascending-j processing + stable insert matches jax.lax.top_k tie order.
// ---------------------------------------------------------------------------
__global__ void knn_kernel(void) {
    __shared__ __align__(16) float4 tile[TILE];
    int b = blockIdx.y;
    int q = blockIdx.x * 256 + threadIdx.x;

    float4 qf = g_xyzw[b * NN + q];
    float nqx = -2.f * qf.x, nqy = -2.f * qf.y, nqz = -2.f * qf.z;

    float bd[KNB];
    int   bi[KNB];
#pragma unroll
    for (int m = 0; m < KNB; m++) { bd[m] = 3.4e38f; bi[m] = -1; }

    for (int t = 0; t < NN / TILE; t++) {
        __syncthreads();
        const float4* src = &g_xyzw[b * NN + t * TILE];
        for (int i = threadIdx.x; i < TILE; i += 256) tile[i] = src[i];
        __syncthreads();

#pragma unroll 4
        for (int j = 0; j < TILE; j++) {
            float4 c = tile[j];
            float d = fmaf(nqx, c.x, fmaf(nqy, c.y, fmaf(nqz, c.z, qf.w + c.w)));
            if (d < bd[KNB - 1]) {
                bd[KNB - 1] = d;
                bi[KNB - 1] = t * TILE + j;
#pragma unroll
                for (int m = KNB - 1; m > 0; m--) {
                    if (bd[m - 1] > bd[m]) {
                        float td = bd[m - 1]; bd[m - 1] = bd[m]; bd[m] = td;
                        int   ti = bi[m - 1]; bi[m - 1] = bi[m]; bi[m] = ti;
                    } else break;
                }
            }
        }
    }

    int4* op = (int4*)(g_idx + ((size_t)b * NN + q) * KNB);
#pragma unroll
    for (int m4 = 0; m4 < KNB / 4; m4++)
        op[m4] = make_int4(bi[m4 * 4 + 0], bi[m4 * 4 + 1],
                           bi[m4 * 4 + 2], bi[m4 * 4 + 3]);
}

// ---------------------------------------------------------------------------
// Kernel 3: gather + 3-layer MLP + max over K neighbors.
// block 128 = 8 queries x 16 neighbor-threads. Weights in smem (broadcast).
// h0,h1 per-thread registers; layer2 in 4-output chunks with shfl_xor max
// reduce over the 16 lanes of each neighbor group; coalesced staged store.
// ---------------------------------------------------------------------------
__global__ void __launch_bounds__(128) mlp_kernel(const float* __restrict__ W0,
                                                  const float* __restrict__ W1,
                                                  const float* __restrict__ W2,
                                                  float* __restrict__ out) {
    __shared__ __align__(16) float w0x[M0][4];    // [o][xyz,pad]
    __shared__ __align__(16) float w1s[M1][M0];   // [o][c]
    __shared__ __align__(16) float w2t[M1][M2];   // transposed: [c][o]
    __shared__ float stage[8][M2];

    int tid = threadIdx.x;
    for (int i = tid; i < M0 * 4; i += 128) {
        int o = i / 4, c = i % 4;
        w0x[o][c] = (c < 3) ? W0[o * 35 + c] : 0.f;
    }
    for (int i = tid; i < M1 * M0; i += 128) {
        int o = i / M0, c = i % M0;
        w1s[o][c] = W1[o * M0 + c];
    }
    for (int i = tid; i < M2 * M1; i += 128) {
        int o = i / M1, c = i % M1;
        w2t[c][o] = W2[i];
    }
    __syncthreads();

    int g = tid >> 4, k = tid & 15;
    int gq = blockIdx.x * 8 + g;        // global query id
    int b = gq / NN, n = gq % NN;

    int j = g_idx[(size_t)gq * KNB + k];
    float4 qf = g_xyzw[gq];
    float4 cf = g_xyzw[b * NN + j];
    float rx = cf.x - qf.x, ry = cf.y - qf.y, rz = cf.z - qf.z;

    // layer 0: h0 = lrelu(W0[:, :3] @ rel + feat[j])
    float h0[M0];
    const float4* fg = (const float4*)(g_feat + ((size_t)b * NN + j) * M0);
#pragma unroll
    for (int o4 = 0; o4 < M0 / 4; o4++) {
        float4 f = fg[o4];
        float fv0 = f.x, fv1 = f.y, fv2 = f.z, fv3 = f.w;
        {
            float4 w = *(const float4*)w0x[o4 * 4 + 0];
            h0[o4 * 4 + 0] = lrelu(fmaf(w.x, rx, fmaf(w.y, ry, fmaf(w.z, rz, fv0))));
        }
        {
            float4 w = *(const float4*)w0x[o4 * 4 + 1];
            h0[o4 * 4 + 1] = lrelu(fmaf(w.x, rx, fmaf(w.y, ry, fmaf(w.z, rz, fv1))));
        }
        {
            float4 w = *(const float4*)w0x[o4 * 4 + 2];
            h0[o4 * 4 + 2] = lrelu(fmaf(w.x, rx, fmaf(w.y, ry, fmaf(w.z, rz, fv2))));
        }
        {
            float4 w = *(const float4*)w0x[o4 * 4 + 3];
            h0[o4 * 4 + 3] = lrelu(fmaf(w.x, rx, fmaf(w.y, ry, fmaf(w.z, rz, fv3))));
        }
    }

    // layer 1: h1 = lrelu(W1 @ h0)
    float h1[M1];
#pragma unroll
    for (int o = 0; o < M1; o++) {
        const float4* w4 = (const float4*)w1s[o];
        float acc = 0.f;
#pragma unroll
        for (int c4 = 0; c4 < M0 / 4; c4++) {
            float4 w = w4[c4];
            acc = fmaf(w.x, h0[c4 * 4 + 0], acc);
            acc = fmaf(w.y, h0[c4 * 4 + 1], acc);
            acc = fmaf(w.z, h0[c4 * 4 + 2], acc);
            acc = fmaf(w.w, h0[c4 * 4 + 3], acc);
        }
        h1[o] = lrelu(acc);
    }

    // layer 2 + lrelu + max over 16 neighbor-lanes, 4 outputs per chunk
    for (int oq = 0; oq < M2 / 4; oq++) {
        float a0 = 0.f, a1 = 0.f, a2 = 0.f, a3 = 0.f;
#pragma unroll
        for (int c = 0; c < M1; c++) {
            float4 w = *(const float4*)&w2t[c][oq * 4];
            float h = h1[c];
            a0 = fmaf(w.x, h, a0);
            a1 = fmaf(w.y, h, a1);
            a2 = fmaf(w.z, h, a2);
            a3 = fmaf(w.w, h, a3);
        }
        a0 = lrelu(a0); a1 = lrelu(a1); a2 = lrelu(a2); a3 = lrelu(a3);
#pragma unroll
        for (int s = 8; s >= 1; s >>= 1) {
            a0 = fmaxf(a0, __shfl_xor_sync(0xffffffffu, a0, s));
            a1 = fmaxf(a1, __shfl_xor_sync(0xffffffffu, a1, s));
            a2 = fmaxf(a2, __shfl_xor_sync(0xffffffffu, a2, s));
            a3 = fmaxf(a3, __shfl_xor_sync(0xffffffffu, a3, s));
        }
        if (k == 0) {
            stage[g][oq * 4 + 0] = a0;
            stage[g][oq * 4 + 1] = a1;
            stage[g][oq * 4 + 2] = a2;
            stage[g][oq * 4 + 3] = a3;
        }
    }
    __syncthreads();

    // coalesced store: out[b][o][n], 8 consecutive n per block
    int gq0 = blockIdx.x * 8;
    int b0 = gq0 / NN, n0 = gq0 % NN;
    for (int i = tid; i < 8 * M2; i += 128) {
        int o = i >> 3, gi = i & 7;
        out[((size_t)b0 * M2 + o) * NN + (n0 + gi)] = stage[gi][o];
    }
}

extern "C" void kernel_launch(void* const* d_in, const int* in_sizes, int n_in,
                              void* d_out, int out_size) {
    const float* xyz    = (const float*)d_in[0];
    const float* points = (const float*)d_in[1];
    const float* W0     = (const float*)d_in[2];
    const float* W1     = (const float*)d_in[3];
    const float* W2     = (const float*)d_in[4];
    float* out = (float*)d_out;

    prep_kernel<<<BB * NN / 128, 128>>>(xyz, points, W0);

    dim3 g2(NN / 256, BB);
    knn_kernel<<<g2, 256>>>();

    mlp_kernel<<<BB * NN / 8, 128>>>(W0, W1, W2, out);
}